// round 14
// baseline (speedup 1.0000x reference)
#include <cuda_runtime.h>
#include <cuda_bf16.h>
#include <stdint.h>

// ---------------- problem dims ----------------
#define BATCH 8
#define CIN   2
#define HH    64
#define WW    64
#define TT    200
#define NCH   7      // ceil(200/32) chunks of 32 timesteps (tail garbage is causal-safe)
#define C1    8
#define C2    8
#define NTAP1 (CIN * 25)   // 50
#define NTAP2 (C1 * 9)     // 72

// fp32 correctly-rounded decay constants
#define D1 0.36787944117144233f   // exp(-1)    : tau=1 (psp1, ref1)
#define D2 0.60653065971263342f   // exp(-1/2)  : tau=2 (psp2, ref2)
#define D3 0.77880078307140487f   // exp(-1/4)  : tau=4 (psp3, ref3)

// LUT entry stride 12 floats (48B): 8 reachable 16B phase-slots for LDS.128.
#define ESTR 12
// L1: 3 LUT groups (c0 taps 0-23) + 4-entry group (taps 24,49) + 24 direct-tap weights (c1 taps 0-23)
#define L1_LUT    (3 * 256 * ESTR)
#define L1_LUT7   (4 * ESTR)
#define SMEM1_FLOATS (L1_LUT + L1_LUT7 + 24 * 8)
// L2: 5 LUT groups (c0-c3 taps 0-7, + cross-channel tap-8) + 32 direct-tap weights (c4-c7 taps 0-7)
#define L2_LUT    (5 * 256 * ESTR)
#define SMEM2_FLOATS (L2_LUT + 32 * 8)

// ---------------- bit-packed intermediates ----------------
__device__ uint32_t g_xbits[BATCH * NCH * CIN * HH * WW];  // 1.75 MB
__device__ uint32_t g_s1  [BATCH * NCH * C1  * HH * WW];   // 7 MB
__device__ uint32_t g_s2  [BATCH * NCH * C2  * HH * WW];   // 7 MB
__device__ uint32_t g_dummy[32];

__device__ __forceinline__ void addf4(float4& a, const float4 b) {
    a.x += b.x; a.y += b.y; a.z += b.z; a.w += b.w;
}

// 8x32 -> per-j byte extraction for one jg (8 timesteps):
// gather byte jg of 8 tap-words, then 8x8 bit transpose.
__device__ __forceinline__ unsigned long long t8x8(const uint32_t* w, int jg) {
    uint32_t s = (uint32_t)jg | (((uint32_t)jg + 4) << 4);
    uint32_t r01 = __byte_perm(w[0], w[1], s);
    uint32_t r23 = __byte_perm(w[2], w[3], s);
    uint32_t r45 = __byte_perm(w[4], w[5], s);
    uint32_t r67 = __byte_perm(w[6], w[7], s);
    uint32_t lo = __byte_perm(r01, r23, 0x5410);
    uint32_t hi = __byte_perm(r45, r67, 0x5410);
    unsigned long long x = (unsigned long long)lo | ((unsigned long long)hi << 32);
    unsigned long long t;
    t = (x ^ (x >> 7))  & 0x00AA00AA00AA00AAull; x = x ^ t ^ (t << 7);
    t = (x ^ (x >> 14)) & 0x0000CCCC0000CCCCull; x = x ^ t ^ (t << 14);
    t = (x ^ (x >> 28)) & 0x00000000F0F0F0F0ull; x = x ^ t ^ (t << 28);
    return x;
}

__device__ __forceinline__ void lutAdd(const float* base, unsigned idx,
                                       float4& lo, float4& hi) {
    const float* e = base + idx * ESTR;
    addf4(lo, *(const float4*)e);
    addf4(hi, *(const float4*)(e + 4));
}

// direct subset-sum in ascending-bit order (bit-identical to chained build)
__device__ __forceinline__ float subsum(const float* wr, int m) {
    float s = 0.f;
#pragma unroll
    for (int p = 0; p < 8; p++)
        if ((m >> p) & 1) s += wr[p];
    return s;
}

// =====================================================================
// Kdummy: trivial launch to keep the ncu capture window on k_layer2.
// =====================================================================
__global__ void k_dummy() {
    if (threadIdx.x < 32) g_dummy[threadIdx.x] = threadIdx.x;
}

// =====================================================================
// K0: binarize + time-transpose input (coalesced ballot version)
// =====================================================================
__global__ void __launch_bounds__(256) k_binarize(const float* __restrict__ x) {
    int gw   = (blockIdx.x * blockDim.x + threadIdx.x) >> 5;   // warp = pixel
    int lane = threadIdx.x & 31;
    if (gw >= BATCH * CIN * HH * WW) return;
    int pix = gw;
    int w = pix % WW; int t1 = pix / WW;
    int h = t1 % HH;  t1 /= HH;
    int c = t1 % CIN; int b = t1 / CIN;
    const float* p = x + (size_t)pix * TT;

    uint32_t words[NCH];
#pragma unroll
    for (int k = 0; k < NCH; k++) {
        int t = k * 32 + lane;
        float v = (t < TT) ? p[t] : 0.f;
        words[k] = __ballot_sync(0xffffffffu, v > 0.5f);
    }
    if (lane < NCH)
        g_xbits[(((b * NCH + lane) * CIN + c) * HH + h) * WW + w] = words[lane];
}

// =====================================================================
// K1: layer 1.  u = IIR_1(conv5x5(xbits)); spike(th=30, dref=D1)
// HYBRID LUT/direct + 2-way t-split: seg0 chunks [0,4); seg1 chunks [4,7)
// warm (no store) from chunk 3 (tau=1: e^-32 residual, numerically exact).
// =====================================================================
__global__ void __launch_bounds__(128) k_layer1(const float* __restrict__ w1) {
    extern __shared__ float dyn[];
    float* lut  = dyn;                       // [3][256][ESTR]  c0 g0-2
    float* lut7 = dyn + L1_LUT;              // [4][ESTR]       taps 24,49
    float* wdir = dyn + L1_LUT + L1_LUT7;    // [24][8]         c1 taps 0-23
    {
        int t = threadIdx.x;
        int o = t & 7, mhi = t >> 3;         // 16 m-values per thread
#pragma unroll 1
        for (int g = 0; g < 3; g++) {
            float wr[8];
#pragma unroll
            for (int p = 0; p < 8; p++) wr[p] = w1[o * NTAP1 + g * 8 + p];
#pragma unroll 1
            for (int i = 0; i < 16; i++) {
                int m = mhi * 16 + i;
                lut[(g * 256 + m) * ESTR + o] = subsum(wr, m);
            }
        }
        if (t < 32) {                        // group7: 4 entries x 8 oc
            int m = t >> 3, o2 = t & 7;
            float wA = w1[o2 * NTAP1 + 24];
            float wB = w1[o2 * NTAP1 + 49];
            lut7[m * ESTR + o2] = ((m & 1) ? wA : 0.f) + ((m & 2) ? wB : 0.f);
        }
        for (int i = t; i < 24 * 8; i += 128) {
            int tap = i >> 3, o2 = i & 7;
            wdir[tap * 8 + o2] = w1[o2 * NTAP1 + 25 + tap];
        }
    }
    __syncthreads();
    const float4* wdirv = (const float4*)wdir;

    int bx  = blockIdx.x;
    int seg = bx >> 8;                       // 0 or 1
    int tid = (bx & 255) * 128 + threadIdx.x;
    int w = tid % WW; int t1 = tid / WW;
    int h = t1 % HH;  int b = t1 / HH;

    int kstart = seg ? 3 : 0;
    int kstore = seg ? 4 : 0;
    int kend   = seg ? NCH : 4;

    float a[C1], r[C1];
#pragma unroll
    for (int o = 0; o < C1; o++) { a[o] = 0.f; r[o] = 0.f; }

    for (int k = kstart; k < kend; k++) {
        uint32_t bits[NTAP1];
#pragma unroll
        for (int c = 0; c < CIN; c++)
#pragma unroll
            for (int dy = 0; dy < 5; dy++)
#pragma unroll
                for (int dx = 0; dx < 5; dx++) {
                    int hh = h + dy - 2, ww = w + dx - 2;
                    uint32_t v = 0;
                    if (hh >= 0 && hh < HH && ww >= 0 && ww < WW)
                        v = g_xbits[(((b * NCH + k) * CIN + c) * HH + hh) * WW + ww];
                    bits[(c * 5 + dy) * 5 + dx] = v;
                }

        uint32_t sb[C1];
#pragma unroll
        for (int o = 0; o < C1; o++) sb[o] = 0u;

#pragma unroll 1
        for (int jg = 0; jg < 4; jg++) {
            float4 sl[8], sh[8];
#pragma unroll
            for (int jj = 0; jj < 8; jj++) {
                sl[jj] = make_float4(0.f, 0.f, 0.f, 0.f);
                sh[jj] = make_float4(0.f, 0.f, 0.f, 0.f);
            }
            // --- LUT path: c0 groups 0-2 ---
#pragma unroll
            for (int g = 0; g < 3; g++) {
                unsigned long long tx = t8x8(bits + g * 8, jg);
                const float* base = lut + (g << 8) * ESTR;
#pragma unroll
                for (int jj = 0; jj < 8; jj++)
                    lutAdd(base, (unsigned)(tx >> (8 * jj)) & 0xFF, sl[jj], sh[jj]);
            }
            // --- group7: taps 24 (c0), 49 (c1) ---
            {
                uint32_t bA = (bits[24] >> (jg * 8)) & 0xFF;
                uint32_t bB = (bits[49] >> (jg * 8)) & 0xFF;
#pragma unroll
                for (int jj = 0; jj < 8; jj++) {
                    unsigned m2 = ((bA >> jj) & 1u) | (((bB >> jj) & 1u) << 1);
                    lutAdd(lut7, m2, sl[jj], sh[jj]);
                }
            }
            // --- direct path: c1 taps 0-23 ---
#pragma unroll 1
            for (int tp = 0; tp < 24; tp++) {
                uint32_t bw = (bits[25 + tp] >> (jg * 8)) & 0xFF;
                float4 w0 = wdirv[tp * 2], w1v = wdirv[tp * 2 + 1];
#pragma unroll
                for (int jj = 0; jj < 8; jj++)
                    if (bw & (1u << jj)) { addf4(sl[jj], w0); addf4(sh[jj], w1v); }
            }
#pragma unroll
            for (int jj = 0; jj < 8; jj++) {
                int j = jg * 8 + jj;
                float su[8] = {sl[jj].x, sl[jj].y, sl[jj].z, sl[jj].w,
                               sh[jj].x, sh[jj].y, sh[jj].z, sh[jj].w};
#pragma unroll
                for (int o = 0; o < C1; o++) {
                    a[o] = D1 * a[o] + su[o];
                    float v = a[o] + r[o];
                    bool hd = v >= 30.0f;
                    sb[o] |= hd ? (1u << j) : 0u;
                    r[o] = D1 * r[o] - (hd ? 30.0f : 0.0f);
                }
            }
        }
        if (k >= kstore) {
#pragma unroll
            for (int o = 0; o < C1; o++)
                g_s1[(((b * NCH + k) * C1 + o) * HH + h) * WW + w] = sb[o];
        }
    }
}

// =====================================================================
// K2: layer 2.  u = IIR_2(conv3x3(s1bits)); spike(th=50, dref=D2)
// HYBRID LUT/direct + 2-way t-split: seg0 chunks [0,4); seg1 chunks [4,7)
// warm from chunk 2 (tau=2: 64 steps = e^-32 residual).
// =====================================================================
__global__ void __launch_bounds__(128) k_layer2(const float* __restrict__ w2) {
    extern __shared__ float dyn[];
    float* lut  = dyn;                       // [5][256][ESTR]
    float* wdir = dyn + L2_LUT;              // [32][8]  c4-c7 taps 0-7
    {
        int t = threadIdx.x;
        int o = t & 7, mhi = t >> 3;
#pragma unroll 1
        for (int c = 0; c < 5; c++) {
            float wr[8];
            if (c < 4) {
#pragma unroll
                for (int p = 0; p < 8; p++) wr[p] = w2[o * NTAP2 + c * 9 + p];
            } else {
#pragma unroll
                for (int p = 0; p < 8; p++) wr[p] = w2[o * NTAP2 + p * 9 + 8];
            }
#pragma unroll 1
            for (int i = 0; i < 16; i++) {
                int m = mhi * 16 + i;
                lut[(c * 256 + m) * ESTR + o] = subsum(wr, m);
            }
        }
        for (int i = t; i < 32 * 8; i += 128) {
            int tap = i >> 3, o2 = i & 7;
            int c = 4 + (tap >> 3), p = tap & 7;
            wdir[tap * 8 + o2] = w2[o2 * NTAP2 + c * 9 + p];
        }
    }
    __syncthreads();
    const float4* wdirv = (const float4*)wdir;

    int bx  = blockIdx.x;
    int seg = bx >> 8;
    int tid = (bx & 255) * 128 + threadIdx.x;
    int w = tid % WW; int t1 = tid / WW;
    int h = t1 % HH;  int b = t1 / HH;

    int kstart = seg ? 2 : 0;
    int kstore = seg ? 4 : 0;
    int kend   = seg ? NCH : 4;

    float a[C2], r[C2];
#pragma unroll
    for (int o = 0; o < C2; o++) { a[o] = 0.f; r[o] = 0.f; }

    for (int k = kstart; k < kend; k++) {
        uint32_t bits[NTAP2];
#pragma unroll
        for (int c = 0; c < C1; c++)
#pragma unroll
            for (int dy = 0; dy < 3; dy++)
#pragma unroll
                for (int dx = 0; dx < 3; dx++) {
                    int hh = h + dy - 1, ww = w + dx - 1;
                    uint32_t v = 0;
                    if (hh >= 0 && hh < HH && ww >= 0 && ww < WW)
                        v = g_s1[(((b * NCH + k) * C1 + c) * HH + hh) * WW + ww];
                    bits[(c * 3 + dy) * 3 + dx] = v;
                }
        uint32_t w8[8];
#pragma unroll
        for (int c = 0; c < 8; c++) w8[c] = bits[c * 9 + 8];

        uint32_t sb[C2];
#pragma unroll
        for (int o = 0; o < C2; o++) sb[o] = 0u;

#pragma unroll 1
        for (int jg = 0; jg < 4; jg++) {
            float4 sl[8], sh[8];
#pragma unroll
            for (int jj = 0; jj < 8; jj++) {
                sl[jj] = make_float4(0.f, 0.f, 0.f, 0.f);
                sh[jj] = make_float4(0.f, 0.f, 0.f, 0.f);
            }
            // --- LUT path: channels 0-3, taps 0-7 ---
#pragma unroll 1
            for (int c = 0; c < 4; c++) {
                unsigned long long tx = t8x8(bits + c * 9, jg);
                const float* base = lut + (c << 8) * ESTR;
#pragma unroll
                for (int jj = 0; jj < 8; jj++)
                    lutAdd(base, (unsigned)(tx >> (8 * jj)) & 0xFF, sl[jj], sh[jj]);
            }
            // --- LUT path: cross-channel tap-8 group ---
            {
                unsigned long long tx = t8x8(w8, jg);
                const float* base = lut + (4 << 8) * ESTR;
#pragma unroll
                for (int jj = 0; jj < 8; jj++)
                    lutAdd(base, (unsigned)(tx >> (8 * jj)) & 0xFF, sl[jj], sh[jj]);
            }
            // --- direct path: channels 4-7, taps 0-7 ---
#pragma unroll 1
            for (int c = 4; c < 8; c++) {
#pragma unroll
                for (int p = 0; p < 8; p++) {
                    uint32_t bw = (bits[c * 9 + p] >> (jg * 8)) & 0xFF;
                    int tap = (c - 4) * 8 + p;
                    float4 w0 = wdirv[tap * 2], w1v = wdirv[tap * 2 + 1];
#pragma unroll
                    for (int jj = 0; jj < 8; jj++)
                        if (bw & (1u << jj)) { addf4(sl[jj], w0); addf4(sh[jj], w1v); }
                }
            }
#pragma unroll
            for (int jj = 0; jj < 8; jj++) {
                int j = jg * 8 + jj;
                float su[8] = {sl[jj].x, sl[jj].y, sl[jj].z, sl[jj].w,
                               sh[jj].x, sh[jj].y, sh[jj].z, sh[jj].w};
#pragma unroll
                for (int o = 0; o < C2; o++) {
                    a[o] = D2 * a[o] + su[o];
                    float v = a[o] + r[o];
                    bool hd = v >= 50.0f;
                    sb[o] |= hd ? (1u << j) : 0u;
                    r[o] = D2 * r[o] - (hd ? 50.0f : 0.0f);
                }
            }
        }
        if (k >= kstore) {
#pragma unroll
            for (int o = 0; o < C2; o++)
                g_s2[(((b * NCH + k) * C2 + o) * HH + h) * WW + w] = sb[o];
        }
    }
}

// =====================================================================
// K3: layer 3 (proven R11/R12 version).
// =====================================================================
__global__ void __launch_bounds__(128) k_layer3(const float* __restrict__ wup,
                                                float* __restrict__ out) {
    __shared__ float swu[64];
    __shared__ float4 lut16[16];
    if (threadIdx.x < 64) swu[threadIdx.x] = wup[threadIdx.x];
    if (threadIdx.x < 16) {
        int n = threadIdx.x;
        lut16[n] = make_float4((n & 1) ? 1.f : 0.f, (n & 2) ? 1.f : 0.f,
                               (n & 4) ? 1.f : 0.f, (n & 8) ? 1.f : 0.f);
    }
    __syncthreads();

    int tid = blockIdx.x * blockDim.x + threadIdx.x;
    int wo = tid & 127; int t1 = tid >> 7;
    int ho = t1 & 127;  int b  = t1 >> 7;
    int hi = ho >> 1, wi = wo >> 1;
    int pa = ho & 1,  pb = wo & 1;

    int r0, r1, c0, c1; float wr0, wr1, wc0, wc1;
    if (!pa) { r0 = (hi > 0) ? hi - 1 : 0;  r1 = hi; wr0 = 0.25f; wr1 = 0.75f; }
    else     { r0 = hi; r1 = (hi < 63) ? hi + 1 : 63; wr0 = 0.75f; wr1 = 0.25f; }
    if (!pb) { c0 = (wi > 0) ? wi - 1 : 0;  c1 = wi; wc0 = 0.25f; wc1 = 0.75f; }
    else     { c0 = wi; c1 = (wi < 63) ? wi + 1 : 63; wc0 = 0.75f; wc1 = 0.25f; }
    float tw00 = wr0 * wc0, tw01 = wr0 * wc1, tw10 = wr1 * wc0, tw11 = wr1 * wc1;

    int lane = threadIdx.x & 31;
    int wo0  = wo & ~31;
    int sub  = lane >> 3;
    int q    = lane & 7;

    float a[2], p[2], rr[2];
#pragma unroll
    for (int o = 0; o < 2; o++) { a[o] = 0.f; p[o] = 0.f; rr[o] = 0.f; }

    for (int k = 0; k < NCH; k++) {
        uint32_t s2b[C2];
#pragma unroll
        for (int c = 0; c < C2; c++)
            s2b[c] = g_s2[(((b * NCH + k) * C2 + c) * HH + hi) * WW + wi];
        uint32_t xb00[2], xb01[2], xb10[2], xb11[2];
#pragma unroll
        for (int c = 0; c < 2; c++) {
            const uint32_t* xp = g_xbits + (size_t)(((b * NCH + k) * CIN) + c) * HH * WW;
            xb00[c] = xp[r0 * WW + c0]; xb01[c] = xp[r0 * WW + c1];
            xb10[c] = xp[r1 * WW + c0]; xb11[c] = xp[r1 * WW + c1];
        }
#pragma unroll 1
        for (int o = 0; o < 2; o++) {
            float sA[32], sX[32];
#pragma unroll
            for (int j = 0; j < 32; j++) { sA[j] = 0.f; sX[j] = 0.f; }
#pragma unroll
            for (int c = 0; c < C2; c++) {
                float wv = swu[((o * 8 + c) * 2 + (1 - pa)) * 2 + (1 - pb)];
                uint32_t bw = s2b[c];
#pragma unroll
                for (int j = 0; j < 32; j++)
                    if (bw & (1u << j)) sA[j] += wv;
            }
            {
                uint32_t bw = xb00[o];
#pragma unroll
                for (int j = 0; j < 32; j++) if (bw & (1u << j)) sX[j] += tw00;
            }
            {
                uint32_t bw = xb01[o];
#pragma unroll
                for (int j = 0; j < 32; j++) if (bw & (1u << j)) sX[j] += tw01;
            }
            {
                uint32_t bw = xb10[o];
#pragma unroll
                for (int j = 0; j < 32; j++) if (bw & (1u << j)) sX[j] += tw10;
            }
            {
                uint32_t bw = xb11[o];
#pragma unroll
                for (int j = 0; j < 32; j++) if (bw & (1u << j)) sX[j] += tw11;
            }
            uint32_t sb = 0;
            float av = a[o], pv = p[o], rv = rr[o];
#pragma unroll
            for (int j = 0; j < 32; j++) {
                av = D3 * av + sA[j];
                pv = D1 * pv + sX[j];
                float v = av + pv + rv;
                bool hd = v >= 100.0f;
                sb |= hd ? (1u << j) : 0u;
                rv = D3 * rv - (hd ? 100.0f : 0.0f);
            }
            a[o] = av; p[o] = pv; rr[o] = rv;

            size_t rowpix = (size_t)((b * 2 + o) * 128 + ho) * 128 + wo0;
            bool qok = (k < NCH - 1) || (q < 2);
#pragma unroll
            for (int it = 0; it < 8; it++) {
                int psrc = it * 4 + sub;
                uint32_t sv = __shfl_sync(0xffffffffu, sb, psrc);
                float4 v = lut16[(sv >> (4 * q)) & 15u];
                if (qok)
                    *(float4*)(out + (rowpix + psrc) * TT + k * 32 + q * 4) = v;
            }
        }
    }
}

// =====================================================================
extern "C" void kernel_launch(void* const* d_in, const int* in_sizes, int n_in,
                              void* d_out, int out_size) {
    const float* x   = (const float*)d_in[0];
    const float* w1  = (const float*)d_in[1];
    const float* w2  = (const float*)d_in[2];
    const float* wup = (const float*)d_in[3];
    float* out = (float*)d_out;

    int smem1 = SMEM1_FLOATS * 4;   // ~37.8 KB
    int smem2 = SMEM2_FLOATS * 4;   // ~62.5 KB
    cudaFuncSetAttribute(k_layer1, cudaFuncAttributeMaxDynamicSharedMemorySize, smem1);
    cudaFuncSetAttribute(k_layer2, cudaFuncAttributeMaxDynamicSharedMemorySize, smem2);

    k_dummy<<<1, 32>>>();                                       // keeps ncu window phase
    int nwarp = BATCH * CIN * HH * WW;                          // 65536 pixel-warps
    k_binarize<<<(nwarp * 32) / 256, 256>>>(x);                 // 8192 blocks
    k_layer1<<<256 * 2, 128, smem1>>>(w1);                      // 512 blocks (t-split)
    k_layer2<<<256 * 2, 128, smem2>>>(w2);                      // 512 blocks (t-split)
    k_layer3<<<(BATCH * 128 * 128) / 128, 128>>>(wup, out);     // 1024 blocks
}

// round 15
// speedup vs baseline: 1.2687x; 1.2687x over previous
#include <cuda_runtime.h>
#include <cuda_bf16.h>
#include <stdint.h>

// ---------------- problem dims ----------------
#define BATCH 8
#define CIN   2
#define HH    64
#define WW    64
#define TT    200
#define NCH   7      // ceil(200/32) chunks of 32 timesteps (tail garbage is causal-safe)
#define C1    8
#define C2    8
#define NTAP1 (CIN * 25)   // 50
#define NTAP2 (C1 * 9)     // 72

// fp32 correctly-rounded decay constants
#define D1 0.36787944117144233f   // exp(-1)    : tau=1 (psp1, ref1)
#define D2 0.60653065971263342f   // exp(-1/2)  : tau=2 (psp2, ref2)
#define D3 0.77880078307140487f   // exp(-1/4)  : tau=4 (psp3, ref3)

// oc-split: each block computes 4 of 8 output channels.
// LUT entry = 4 floats (16B): start slot = m mod 8 -> all 8 phase-slots reachable.
#define ESTR4 4
// L1: 3 LUT groups (c0 taps 0-23) + 4-entry group (taps 24,49) + 24 direct taps (c1)
#define L1_LUT    (3 * 256 * ESTR4)
#define L1_LUT7   (4 * ESTR4)
#define SMEM1_FLOATS (L1_LUT + L1_LUT7 + 24 * 4)
// L2: 5 LUT groups (c0-c3 taps 0-7 + cross-channel tap-8) + 32 direct taps (c4-c7)
#define L2_LUT    (5 * 256 * ESTR4)
#define SMEM2_FLOATS (L2_LUT + 32 * 4)

// ---------------- bit-packed intermediates ----------------
__device__ uint32_t g_xbits[BATCH * NCH * CIN * HH * WW];  // 1.75 MB
__device__ uint32_t g_s1  [BATCH * NCH * C1  * HH * WW];   // 7 MB
__device__ uint32_t g_s2  [BATCH * NCH * C2  * HH * WW];   // 7 MB
__device__ uint32_t g_dummy[32];

__device__ __forceinline__ void addf4(float4& a, const float4 b) {
    a.x += b.x; a.y += b.y; a.z += b.z; a.w += b.w;
}

// 8x32 -> per-j byte extraction for one jg (8 timesteps):
// gather byte jg of 8 tap-words, then 8x8 bit transpose.
__device__ __forceinline__ unsigned long long t8x8(const uint32_t* w, int jg) {
    uint32_t s = (uint32_t)jg | (((uint32_t)jg + 4) << 4);
    uint32_t r01 = __byte_perm(w[0], w[1], s);
    uint32_t r23 = __byte_perm(w[2], w[3], s);
    uint32_t r45 = __byte_perm(w[4], w[5], s);
    uint32_t r67 = __byte_perm(w[6], w[7], s);
    uint32_t lo = __byte_perm(r01, r23, 0x5410);
    uint32_t hi = __byte_perm(r45, r67, 0x5410);
    unsigned long long x = (unsigned long long)lo | ((unsigned long long)hi << 32);
    unsigned long long t;
    t = (x ^ (x >> 7))  & 0x00AA00AA00AA00AAull; x = x ^ t ^ (t << 7);
    t = (x ^ (x >> 14)) & 0x0000CCCC0000CCCCull; x = x ^ t ^ (t << 14);
    t = (x ^ (x >> 28)) & 0x00000000F0F0F0F0ull; x = x ^ t ^ (t << 28);
    return x;
}

// direct subset-sum in ascending-bit order (bit-identical to chained build)
__device__ __forceinline__ float subsum(const float* wr, int m) {
    float s = 0.f;
#pragma unroll
    for (int p = 0; p < 8; p++)
        if ((m >> p) & 1) s += wr[p];
    return s;
}

// =====================================================================
// Kdummy: trivial launch to keep the ncu capture window on k_layer2.
// =====================================================================
__global__ void k_dummy() {
    if (threadIdx.x < 32) g_dummy[threadIdx.x] = threadIdx.x;
}

// =====================================================================
// K0: binarize + time-transpose input (coalesced ballot version)
// =====================================================================
__global__ void __launch_bounds__(256) k_binarize(const float* __restrict__ x) {
    int gw   = (blockIdx.x * blockDim.x + threadIdx.x) >> 5;   // warp = pixel
    int lane = threadIdx.x & 31;
    if (gw >= BATCH * CIN * HH * WW) return;
    int pix = gw;
    int w = pix % WW; int t1 = pix / WW;
    int h = t1 % HH;  t1 /= HH;
    int c = t1 % CIN; int b = t1 / CIN;
    const float* p = x + (size_t)pix * TT;

    uint32_t words[NCH];
#pragma unroll
    for (int k = 0; k < NCH; k++) {
        int t = k * 32 + lane;
        float v = (t < TT) ? p[t] : 0.f;
        words[k] = __ballot_sync(0xffffffffu, v > 0.5f);
    }
    if (lane < NCH)
        g_xbits[(((b * NCH + lane) * CIN + c) * HH + h) * WW + w] = words[lane];
}

// =====================================================================
// K1: layer 1.  u = IIR_1(conv5x5(xbits)); spike(th=30, dref=D1)
// oc-split x2: block handles oc [ocg*4, ocg*4+4). 4-float LUT entries.
// grid = 256 pixblocks x 2 ocgroups.
// =====================================================================
__global__ void __launch_bounds__(128) k_layer1(const float* __restrict__ w1) {
    extern __shared__ float dyn[];
    float* lut  = dyn;                       // [3][256][4]
    float* lut7 = dyn + L1_LUT;              // [4][4]
    float* wdir = dyn + L1_LUT + L1_LUT7;    // [24][4]
    int bx  = blockIdx.x;
    int ocg = bx >> 8;                       // 0 or 1
    int oc0 = ocg * 4;
    {
        int t = threadIdx.x;
        int o = t & 3, mhi = t >> 2;         // 8 m-values per thread (32 mhi x 8)
#pragma unroll 1
        for (int g = 0; g < 3; g++) {
            float wr[8];
#pragma unroll
            for (int p = 0; p < 8; p++) wr[p] = w1[(oc0 + o) * NTAP1 + g * 8 + p];
#pragma unroll 1
            for (int i = 0; i < 8; i++) {
                int m = mhi * 8 + i;
                lut[(g * 256 + m) * ESTR4 + o] = subsum(wr, m);
            }
        }
        if (t < 16) {                        // group7: 4 entries x 4 oc
            int m = t >> 2, o2 = t & 3;
            float wA = w1[(oc0 + o2) * NTAP1 + 24];
            float wB = w1[(oc0 + o2) * NTAP1 + 49];
            lut7[m * ESTR4 + o2] = ((m & 1) ? wA : 0.f) + ((m & 2) ? wB : 0.f);
        }
        if (t < 96) {                        // 24 taps x 4 oc
            int tap = t >> 2, o2 = t & 3;
            wdir[tap * 4 + o2] = w1[(oc0 + o2) * NTAP1 + 25 + tap];
        }
    }
    __syncthreads();
    const float4* lutv  = (const float4*)lut;
    const float4* lut7v = (const float4*)lut7;
    const float4* wdirv = (const float4*)wdir;

    int tid = (bx & 255) * 128 + threadIdx.x;
    int w = tid % WW; int t1 = tid / WW;
    int h = t1 % HH;  int b = t1 / HH;

    float a[4], r[4];
#pragma unroll
    for (int o = 0; o < 4; o++) { a[o] = 0.f; r[o] = 0.f; }

    for (int k = 0; k < NCH; k++) {
        uint32_t bits[NTAP1];
#pragma unroll
        for (int c = 0; c < CIN; c++)
#pragma unroll
            for (int dy = 0; dy < 5; dy++)
#pragma unroll
                for (int dx = 0; dx < 5; dx++) {
                    int hh = h + dy - 2, ww = w + dx - 2;
                    uint32_t v = 0;
                    if (hh >= 0 && hh < HH && ww >= 0 && ww < WW)
                        v = g_xbits[(((b * NCH + k) * CIN + c) * HH + hh) * WW + ww];
                    bits[(c * 5 + dy) * 5 + dx] = v;
                }

        uint32_t sb[4];
#pragma unroll
        for (int o = 0; o < 4; o++) sb[o] = 0u;

#pragma unroll 1
        for (int jg = 0; jg < 4; jg++) {
            float4 sl[8];
#pragma unroll
            for (int jj = 0; jj < 8; jj++) sl[jj] = make_float4(0.f, 0.f, 0.f, 0.f);
            // --- LUT path: c0 groups 0-2 ---
#pragma unroll
            for (int g = 0; g < 3; g++) {
                unsigned long long tx = t8x8(bits + g * 8, jg);
#pragma unroll
                for (int jj = 0; jj < 8; jj++) {
                    unsigned m = (unsigned)(tx >> (8 * jj)) & 0xFF;
                    addf4(sl[jj], lutv[(g << 8) | m]);
                }
            }
            // --- group7: taps 24 (c0), 49 (c1) ---
            {
                uint32_t bA = (bits[24] >> (jg * 8)) & 0xFF;
                uint32_t bB = (bits[49] >> (jg * 8)) & 0xFF;
#pragma unroll
                for (int jj = 0; jj < 8; jj++) {
                    unsigned m2 = ((bA >> jj) & 1u) | (((bB >> jj) & 1u) << 1);
                    addf4(sl[jj], lut7v[m2]);
                }
            }
            // --- direct path: c1 taps 0-23 ---
#pragma unroll 1
            for (int tp = 0; tp < 24; tp++) {
                uint32_t bw = (bits[25 + tp] >> (jg * 8)) & 0xFF;
                float4 w0 = wdirv[tp];
#pragma unroll
                for (int jj = 0; jj < 8; jj++)
                    if (bw & (1u << jj)) addf4(sl[jj], w0);
            }
#pragma unroll
            for (int jj = 0; jj < 8; jj++) {
                int j = jg * 8 + jj;
                float su[4] = {sl[jj].x, sl[jj].y, sl[jj].z, sl[jj].w};
#pragma unroll
                for (int o = 0; o < 4; o++) {
                    a[o] = D1 * a[o] + su[o];
                    float v = a[o] + r[o];
                    bool hd = v >= 30.0f;
                    sb[o] |= hd ? (1u << j) : 0u;
                    r[o] = D1 * r[o] - (hd ? 30.0f : 0.0f);
                }
            }
        }
#pragma unroll
        for (int o = 0; o < 4; o++)
            g_s1[(((b * NCH + k) * C1 + (oc0 + o)) * HH + h) * WW + w] = sb[o];
    }
}

// =====================================================================
// K2: layer 2.  u = IIR_2(conv3x3(s1bits)); spike(th=50, dref=D2)
// oc-split x2, 4-float LUT entries, hybrid LUT/direct.
// =====================================================================
__global__ void __launch_bounds__(128) k_layer2(const float* __restrict__ w2) {
    extern __shared__ float dyn[];
    float* lut  = dyn;                       // [5][256][4]
    float* wdir = dyn + L2_LUT;              // [32][4]
    int bx  = blockIdx.x;
    int ocg = bx >> 8;
    int oc0 = ocg * 4;
    {
        int t = threadIdx.x;
        int o = t & 3, mhi = t >> 2;
#pragma unroll 1
        for (int c = 0; c < 5; c++) {
            float wr[8];
            if (c < 4) {
#pragma unroll
                for (int p = 0; p < 8; p++) wr[p] = w2[(oc0 + o) * NTAP2 + c * 9 + p];
            } else {
#pragma unroll
                for (int p = 0; p < 8; p++) wr[p] = w2[(oc0 + o) * NTAP2 + p * 9 + 8];
            }
#pragma unroll 1
            for (int i = 0; i < 8; i++) {
                int m = mhi * 8 + i;
                lut[(c * 256 + m) * ESTR4 + o] = subsum(wr, m);
            }
        }
        if (t < 128) {                       // 32 taps x 4 oc
            int tap = t >> 2, o2 = t & 3;
            int c = 4 + (tap >> 3), p = tap & 7;
            wdir[tap * 4 + o2] = w2[(oc0 + o2) * NTAP2 + c * 9 + p];
        }
    }
    __syncthreads();
    const float4* lutv  = (const float4*)lut;
    const float4* wdirv = (const float4*)wdir;

    int tid = (bx & 255) * 128 + threadIdx.x;
    int w = tid % WW; int t1 = tid / WW;
    int h = t1 % HH;  int b = t1 / HH;

    float a[4], r[4];
#pragma unroll
    for (int o = 0; o < 4; o++) { a[o] = 0.f; r[o] = 0.f; }

    for (int k = 0; k < NCH; k++) {
        uint32_t bits[NTAP2];
#pragma unroll
        for (int c = 0; c < C1; c++)
#pragma unroll
            for (int dy = 0; dy < 3; dy++)
#pragma unroll
                for (int dx = 0; dx < 3; dx++) {
                    int hh = h + dy - 1, ww = w + dx - 1;
                    uint32_t v = 0;
                    if (hh >= 0 && hh < HH && ww >= 0 && ww < WW)
                        v = g_s1[(((b * NCH + k) * C1 + c) * HH + hh) * WW + ww];
                    bits[(c * 3 + dy) * 3 + dx] = v;
                }
        uint32_t w8[8];
#pragma unroll
        for (int c = 0; c < 8; c++) w8[c] = bits[c * 9 + 8];

        uint32_t sb[4];
#pragma unroll
        for (int o = 0; o < 4; o++) sb[o] = 0u;

#pragma unroll 1
        for (int jg = 0; jg < 4; jg++) {
            float4 sl[8];
#pragma unroll
            for (int jj = 0; jj < 8; jj++) sl[jj] = make_float4(0.f, 0.f, 0.f, 0.f);
            // --- LUT path: channels 0-3, taps 0-7 ---
#pragma unroll 1
            for (int c = 0; c < 4; c++) {
                unsigned long long tx = t8x8(bits + c * 9, jg);
#pragma unroll
                for (int jj = 0; jj < 8; jj++) {
                    unsigned m = (unsigned)(tx >> (8 * jj)) & 0xFF;
                    addf4(sl[jj], lutv[(c << 8) | m]);
                }
            }
            // --- LUT path: cross-channel tap-8 group ---
            {
                unsigned long long tx = t8x8(w8, jg);
#pragma unroll
                for (int jj = 0; jj < 8; jj++) {
                    unsigned m = (unsigned)(tx >> (8 * jj)) & 0xFF;
                    addf4(sl[jj], lutv[(4 << 8) | m]);
                }
            }
            // --- direct path: channels 4-7, taps 0-7 ---
#pragma unroll 1
            for (int c = 4; c < 8; c++) {
#pragma unroll
                for (int p = 0; p < 8; p++) {
                    uint32_t bw = (bits[c * 9 + p] >> (jg * 8)) & 0xFF;
                    float4 w0 = wdirv[(c - 4) * 8 + p];
#pragma unroll
                    for (int jj = 0; jj < 8; jj++)
                        if (bw & (1u << jj)) addf4(sl[jj], w0);
                }
            }
#pragma unroll
            for (int jj = 0; jj < 8; jj++) {
                int j = jg * 8 + jj;
                float su[4] = {sl[jj].x, sl[jj].y, sl[jj].z, sl[jj].w};
#pragma unroll
                for (int o = 0; o < 4; o++) {
                    a[o] = D2 * a[o] + su[o];
                    float v = a[o] + r[o];
                    bool hd = v >= 50.0f;
                    sb[o] |= hd ? (1u << j) : 0u;
                    r[o] = D2 * r[o] - (hd ? 50.0f : 0.0f);
                }
            }
        }
#pragma unroll
        for (int o = 0; o < 4; o++)
            g_s2[(((b * NCH + k) * C2 + (oc0 + o)) * HH + h) * WW + w] = sb[o];
    }
}

// =====================================================================
// K3: layer 3 (proven R11/R12 version).
// =====================================================================
__global__ void __launch_bounds__(128) k_layer3(const float* __restrict__ wup,
                                                float* __restrict__ out) {
    __shared__ float swu[64];
    __shared__ float4 lut16[16];
    if (threadIdx.x < 64) swu[threadIdx.x] = wup[threadIdx.x];
    if (threadIdx.x < 16) {
        int n = threadIdx.x;
        lut16[n] = make_float4((n & 1) ? 1.f : 0.f, (n & 2) ? 1.f : 0.f,
                               (n & 4) ? 1.f : 0.f, (n & 8) ? 1.f : 0.f);
    }
    __syncthreads();

    int tid = blockIdx.x * blockDim.x + threadIdx.x;
    int wo = tid & 127; int t1 = tid >> 7;
    int ho = t1 & 127;  int b  = t1 >> 7;
    int hi = ho >> 1, wi = wo >> 1;
    int pa = ho & 1,  pb = wo & 1;

    int r0, r1, c0, c1; float wr0, wr1, wc0, wc1;
    if (!pa) { r0 = (hi > 0) ? hi - 1 : 0;  r1 = hi; wr0 = 0.25f; wr1 = 0.75f; }
    else     { r0 = hi; r1 = (hi < 63) ? hi + 1 : 63; wr0 = 0.75f; wr1 = 0.25f; }
    if (!pb) { c0 = (wi > 0) ? wi - 1 : 0;  c1 = wi; wc0 = 0.25f; wc1 = 0.75f; }
    else     { c0 = wi; c1 = (wi < 63) ? wi + 1 : 63; wc0 = 0.75f; wc1 = 0.25f; }
    float tw00 = wr0 * wc0, tw01 = wr0 * wc1, tw10 = wr1 * wc0, tw11 = wr1 * wc1;

    int lane = threadIdx.x & 31;
    int wo0  = wo & ~31;
    int sub  = lane >> 3;
    int q    = lane & 7;

    float a[2], p[2], rr[2];
#pragma unroll
    for (int o = 0; o < 2; o++) { a[o] = 0.f; p[o] = 0.f; rr[o] = 0.f; }

    for (int k = 0; k < NCH; k++) {
        uint32_t s2b[C2];
#pragma unroll
        for (int c = 0; c < C2; c++)
            s2b[c] = g_s2[(((b * NCH + k) * C2 + c) * HH + hi) * WW + wi];
        uint32_t xb00[2], xb01[2], xb10[2], xb11[2];
#pragma unroll
        for (int c = 0; c < 2; c++) {
            const uint32_t* xp = g_xbits + (size_t)(((b * NCH + k) * CIN) + c) * HH * WW;
            xb00[c] = xp[r0 * WW + c0]; xb01[c] = xp[r0 * WW + c1];
            xb10[c] = xp[r1 * WW + c0]; xb11[c] = xp[r1 * WW + c1];
        }
#pragma unroll 1
        for (int o = 0; o < 2; o++) {
            float sA[32], sX[32];
#pragma unroll
            for (int j = 0; j < 32; j++) { sA[j] = 0.f; sX[j] = 0.f; }
#pragma unroll
            for (int c = 0; c < C2; c++) {
                float wv = swu[((o * 8 + c) * 2 + (1 - pa)) * 2 + (1 - pb)];
                uint32_t bw = s2b[c];
#pragma unroll
                for (int j = 0; j < 32; j++)
                    if (bw & (1u << j)) sA[j] += wv;
            }
            {
                uint32_t bw = xb00[o];
#pragma unroll
                for (int j = 0; j < 32; j++) if (bw & (1u << j)) sX[j] += tw00;
            }
            {
                uint32_t bw = xb01[o];
#pragma unroll
                for (int j = 0; j < 32; j++) if (bw & (1u << j)) sX[j] += tw01;
            }
            {
                uint32_t bw = xb10[o];
#pragma unroll
                for (int j = 0; j < 32; j++) if (bw & (1u << j)) sX[j] += tw10;
            }
            {
                uint32_t bw = xb11[o];
#pragma unroll
                for (int j = 0; j < 32; j++) if (bw & (1u << j)) sX[j] += tw11;
            }
            uint32_t sb = 0;
            float av = a[o], pv = p[o], rv = rr[o];
#pragma unroll
            for (int j = 0; j < 32; j++) {
                av = D3 * av + sA[j];
                pv = D1 * pv + sX[j];
                float v = av + pv + rv;
                bool hd = v >= 100.0f;
                sb |= hd ? (1u << j) : 0u;
                rv = D3 * rv - (hd ? 100.0f : 0.0f);
            }
            a[o] = av; p[o] = pv; rr[o] = rv;

            size_t rowpix = (size_t)((b * 2 + o) * 128 + ho) * 128 + wo0;
            bool qok = (k < NCH - 1) || (q < 2);
#pragma unroll
            for (int it = 0; it < 8; it++) {
                int psrc = it * 4 + sub;
                uint32_t sv = __shfl_sync(0xffffffffu, sb, psrc);
                float4 v = lut16[(sv >> (4 * q)) & 15u];
                if (qok)
                    *(float4*)(out + (rowpix + psrc) * TT + k * 32 + q * 4) = v;
            }
        }
    }
}

// =====================================================================
extern "C" void kernel_launch(void* const* d_in, const int* in_sizes, int n_in,
                              void* d_out, int out_size) {
    const float* x   = (const float*)d_in[0];
    const float* w1  = (const float*)d_in[1];
    const float* w2  = (const float*)d_in[2];
    const float* wup = (const float*)d_in[3];
    float* out = (float*)d_out;

    int smem1 = SMEM1_FLOATS * 4;   // ~12.7 KB
    int smem2 = SMEM2_FLOATS * 4;   // ~21.0 KB
    cudaFuncSetAttribute(k_layer1, cudaFuncAttributeMaxDynamicSharedMemorySize, smem1);
    cudaFuncSetAttribute(k_layer2, cudaFuncAttributeMaxDynamicSharedMemorySize, smem2);

    k_dummy<<<1, 32>>>();                                       // keeps ncu window phase
    int nwarp = BATCH * CIN * HH * WW;                          // 65536 pixel-warps
    k_binarize<<<(nwarp * 32) / 256, 256>>>(x);                 // 8192 blocks
    k_layer1<<<256 * 2, 128, smem1>>>(w1);                      // 512 blocks (oc-split)
    k_layer2<<<256 * 2, 128, smem2>>>(w2);                      // 512 blocks (oc-split)
    k_layer3<<<(BATCH * 128 * 128) / 128, 128>>>(wup, out);     // 1024 blocks
}